// round 16
// baseline (speedup 1.0000x reference)
#include <cuda_runtime.h>

// Laplacian_Forward_Model — column-per-lane, smem-free stencil, 2 warps/image.
// CTA = 128 threads = 4 warps = 2 images. Warp pair (2h, 2h+1) covers rows
// [0,16) and [16,32) of image blockIdx.x*2+h; lane = column. Streaming 3-row
// h-window conv (no STS/LDS); REDUX.S32 warp reduction + tiny smem pair-combine.
//
// input (B,1,32,32) f32; weight (n_mult,9); weight_factor (n_mult,1);
// output (n_mult,B,1,32,32) f32.

#define TPB 128

// Order-preserving float<->int map (self-inverse, monotone for finite values).
__device__ __forceinline__ int f2ord(float x) {
    int b = __float_as_int(x);
    return b ^ ((b >> 31) & 0x7FFFFFFF);
}
__device__ __forceinline__ float ord2f(int k) {
    return __int_as_float(k ^ ((k >> 31) & 0x7FFFFFFF));
}
__device__ __forceinline__ float fma_sat(float a, float b, float c) {
    float r;
    asm("fma.rn.sat.f32 %0, %1, %2, %3;" : "=f"(r) : "f"(a), "f"(b), "f"(c));
    return r;
}
__device__ __forceinline__ void stg_cs(float* p, float v) {
    asm volatile("st.global.cs.f32 [%0], %1;" :: "l"(p), "f"(v) : "memory");
}

__global__ __launch_bounds__(TPB, 10)
void lap_fwd_kernel(const float* __restrict__ in,
                    const float* __restrict__ weight,
                    const float* __restrict__ wfac,
                    float* __restrict__ out,
                    int B)
{
    __shared__ int smn1[4], smx1[4], smn2[4], smx2[4];

    const int tid  = threadIdx.x;
    const int wid  = tid >> 5;
    const int lane = tid & 31;
    const int img  = (blockIdx.x << 1) | (wid >> 1);  // image of this warp
    const int y0   = (wid & 1) << 4;                  // row-half base: 0 or 16
    const int pw   = wid ^ 1;                         // partner warp
    const int ii   = blockIdx.y;
    const unsigned FULL = 0xffffffffu;

    const bool valid = (img < B);
    const int  imgc  = valid ? img : 0;               // clamped for safe loads

    // ---- clamped 3x3 kernel (broadcast loads) ----
    float wfv = fminf(fmaxf(wfac[ii], 1.001f), 254.999f);
    float k[9];
#pragma unroll
    for (int j = 0; j < 9; ++j) {
        float w = weight[ii * 9 + j];
        k[j] = fminf(fmaxf(w, -0.999f), 0.999f) * wfv;
    }

    const float* src = in + (size_t)imgc * 1024 + lane;   // this lane's column

    // ---- pass 1: streaming 3x3 conv over rows [y0, y0+16) ----
    // iterate absolute rows ya = y0-1 .. y0+16 (18 rows incl. halo)
    float cv[16];
    float h0p = 0.0f, pp = 0.0f;
#pragma unroll
    for (int yy = 0; yy < 18; ++yy) {
        int ya = y0 - 1 + yy;
        float x = (ya >= 0 && ya < 32) ? src[ya * 32] : 0.0f;
        float L = __shfl_up_sync(FULL, x, 1);
        float R = __shfl_down_sync(FULL, x, 1);
        if (lane == 0)  L = 0.0f;
        if (lane == 31) R = 0.0f;
        float h0 = k[0] * L + k[1] * x + k[2] * R;
        float h1 = k[3] * L + k[4] * x + k[5] * R;
        float h2 = k[6] * L + k[7] * x + k[8] * R;
        if (yy >= 2) cv[yy - 2] = pp + h2;     // conv of row ya-1
        pp  = h0p + h1;
        h0p = h0;
    }

    // ---- reduction 1: warp REDUX + 2-warp smem combine ----
    float mn = cv[0], mx = cv[0];
#pragma unroll
    for (int j = 1; j < 16; ++j) { mn = fminf(mn, cv[j]); mx = fmaxf(mx, cv[j]); }
    int mni = __reduce_min_sync(FULL, f2ord(mn));
    int mxi = __reduce_max_sync(FULL, f2ord(mx));
    if (lane == 0) { smn1[wid] = mni; smx1[wid] = mxi; }
    __syncthreads();
    float cmin = ord2f(min(smn1[wid], smn1[pw]));
    float cmax = ord2f(max(smx1[wid], smx1[pw]));

    // ---- pass 2: sharpen in place (x reloaded; L1-resident) ----
    float s1 = 255.0f / fmaxf(cmax - cmin, 1e-6f);   // image-uniform
#pragma unroll
    for (int i = 0; i < 16; ++i) {
        float x = __ldg(src + (y0 + i) * 32);
        cv[i] = fmaf(cv[i] - cmin, s1, x);
    }

    // ---- reduction 2 ----
    mn = cv[0]; mx = cv[0];
#pragma unroll
    for (int j = 1; j < 16; ++j) { mn = fminf(mn, cv[j]); mx = fmaxf(mx, cv[j]); }
    mni = __reduce_min_sync(FULL, f2ord(mn));
    mxi = __reduce_max_sync(FULL, f2ord(mx));
    if (lane == 0) { smn2[wid] = mni; smx2[wid] = mxi; }
    __syncthreads();
    float smin = ord2f(min(smn2[wid], smn2[pw]));
    float smax = ord2f(max(smx2[wid], smx2[pw]));

    // ---- pass 3: u = sat((sh-smin)*invd); out = floor(255*u) ----
    float invd = 1.0f / fminf(fmaxf(smax - smin, 1e-6f), 255.0f);
    float d2   = -smin * invd;
    if (valid) {
        float* dst = out + ((size_t)ii * B + img) * 1024 + lane;
#pragma unroll
        for (int i = 0; i < 16; ++i) {
            float u = fma_sat(cv[i], invd, d2);   // free [0,1] clamp
            stg_cs(dst + (y0 + i) * 32, floorf(u * 255.0f));
        }
    }
}

extern "C" void kernel_launch(void* const* d_in, const int* in_sizes, int n_in,
                              void* d_out, int out_size)
{
    const float* in  = (const float*)d_in[0];
    const float* w   = (const float*)d_in[1];
    const float* wf  = (const float*)d_in[2];
    float* out       = (float*)d_out;

    int B      = in_sizes[0] / 1024;
    int n_mult = in_sizes[1] / 9;

    dim3 grid((B + 1) / 2, n_mult);
    lap_fwd_kernel<<<grid, TPB>>>(in, w, wf, out, B);
}

// round 17
// speedup vs baseline: 1.0667x; 1.0667x over previous
#include <cuda_runtime.h>

// Laplacian_Forward_Model — column-per-lane, smem-free, barrier-free (R14 core)
// R17 = R14 + launch_bounds(128,9) (regs<=56 -> 36 warps/SM) + 4-way ILP
// min/max reduction chains (was 31-deep serial).
//
// input (B,1,32,32) f32; weight (n_mult,9); weight_factor (n_mult,1);
// output (n_mult,B,1,32,32) f32.

#define TPB 128

// Order-preserving float<->int map (self-inverse, monotone for finite values).
__device__ __forceinline__ int f2ord(float x) {
    int b = __float_as_int(x);
    return b ^ ((b >> 31) & 0x7FFFFFFF);
}
__device__ __forceinline__ float ord2f(int k) {
    return __int_as_float(k ^ ((k >> 31) & 0x7FFFFFFF));
}
__device__ __forceinline__ float fma_sat(float a, float b, float c) {
    float r;
    asm("fma.rn.sat.f32 %0, %1, %2, %3;" : "=f"(r) : "f"(a), "f"(b), "f"(c));
    return r;
}
__device__ __forceinline__ void stg_cs(float* p, float v) {
    asm volatile("st.global.cs.f32 [%0], %1;" :: "l"(p), "f"(v) : "memory");
}

// 4-way ILP min/max over 32 values (4 independent 8-deep chains + combine).
__device__ __forceinline__ void minmax32(const float* v, float& mn, float& mx) {
    float n0 = v[0], n1 = v[1], n2 = v[2], n3 = v[3];
    float x0 = v[0], x1 = v[1], x2 = v[2], x3 = v[3];
#pragma unroll
    for (int j = 4; j < 32; j += 4) {
        n0 = fminf(n0, v[j]);     x0 = fmaxf(x0, v[j]);
        n1 = fminf(n1, v[j + 1]); x1 = fmaxf(x1, v[j + 1]);
        n2 = fminf(n2, v[j + 2]); x2 = fmaxf(x2, v[j + 2]);
        n3 = fminf(n3, v[j + 3]); x3 = fmaxf(x3, v[j + 3]);
    }
    mn = fminf(fminf(n0, n1), fminf(n2, n3));
    mx = fmaxf(fmaxf(x0, x1), fmaxf(x2, x3));
}

__global__ __launch_bounds__(TPB, 9)
void lap_fwd_kernel(const float* __restrict__ in,
                    const float* __restrict__ weight,
                    const float* __restrict__ wfac,
                    float* __restrict__ out,
                    int B)
{
    const int tid  = threadIdx.x;
    const int wid  = tid >> 5;
    const int lane = tid & 31;
    const int b    = blockIdx.x * 4 + wid;   // image index (one per warp)
    const int ii   = blockIdx.y;
    const unsigned FULL = 0xffffffffu;

    if (b >= B) return;               // warp-uniform

    // ---- clamped 3x3 kernel (broadcast loads) ----
    float wfv = fminf(fmaxf(wfac[ii], 1.001f), 254.999f);
    float k[9];
#pragma unroll
    for (int j = 0; j < 9; ++j) {
        float w = weight[ii * 9 + j];
        k[j] = fminf(fmaxf(w, -0.999f), 0.999f) * wfv;
    }

    const float* src = in + (size_t)b * 1024 + lane;   // this lane's column

    // ---- pass 1: streaming 3x3 conv, cv[y] per lane-column ----
    // conv(y) = h0(y-1) + h1(y) + h2(y+1), ht(y) = k[3t]*L + k[3t+1]*x + k[3t+2]*R
    float cv[32];
    float h0p = 0.0f;     // h0 of previous row (row -1 = zero padding)
    float pp  = 0.0f;     // partial h0(y-1)+h1(y) awaiting h2(y+1)
#pragma unroll
    for (int y = 0; y < 32; ++y) {
        float x = src[y * 32];                     // coalesced 128B row load
        float L = __shfl_up_sync(FULL, x, 1);
        float R = __shfl_down_sync(FULL, x, 1);
        if (lane == 0)  L = 0.0f;
        if (lane == 31) R = 0.0f;
        float h0 = k[0] * L + k[1] * x + k[2] * R;
        float h1 = k[3] * L + k[4] * x + k[5] * R;
        float h2 = k[6] * L + k[7] * x + k[8] * R;
        if (y > 0) cv[y - 1] = pp + h2;
        pp  = h0p + h1;
        h0p = h0;
    }
    cv[31] = pp;                                   // h2(row 32) = 0

    // ---- reduction 1: 4-way local tree + warp REDUX ----
    float mn, mx;
    minmax32(cv, mn, mx);
    float cmin = ord2f(__reduce_min_sync(FULL, f2ord(mn)));
    float cmax = ord2f(__reduce_max_sync(FULL, f2ord(mx)));

    // ---- pass 2: sharpen in place (x reloaded; L1D-resident) ----
    float s1 = 255.0f / fmaxf(cmax - cmin, 1e-6f);   // warp-uniform
#pragma unroll
    for (int y = 0; y < 32; ++y) {
        float x = __ldg(src + y * 32);               // L1 hit
        cv[y] = fmaf(cv[y] - cmin, s1, x);
    }

    // ---- reduction 2: 4-way local tree + warp REDUX ----
    minmax32(cv, mn, mx);
    float smin = ord2f(__reduce_min_sync(FULL, f2ord(mn)));
    float smax = ord2f(__reduce_max_sync(FULL, f2ord(mx)));

    // ---- pass 3: u = sat((sh-smin)*invd); out = floor(255*u); STG.32/row ----
    float invd = 1.0f / fminf(fmaxf(smax - smin, 1e-6f), 255.0f);
    float d2   = -smin * invd;
    float* dst = out + ((size_t)ii * B + b) * 1024 + lane;
#pragma unroll
    for (int y = 0; y < 32; ++y) {
        float u = fma_sat(cv[y], invd, d2);          // free [0,1] clamp
        stg_cs(dst + y * 32, floorf(u * 255.0f));
    }
}

extern "C" void kernel_launch(void* const* d_in, const int* in_sizes, int n_in,
                              void* d_out, int out_size)
{
    const float* in  = (const float*)d_in[0];
    const float* w   = (const float*)d_in[1];
    const float* wf  = (const float*)d_in[2];
    float* out       = (float*)d_out;

    int B      = in_sizes[0] / 1024;
    int n_mult = in_sizes[1] / 9;

    dim3 grid((B + 3) / 4, n_mult);
    lap_fwd_kernel<<<grid, TPB>>>(in, w, wf, out, B);
}